// round 5
// baseline (speedup 1.0000x reference)
#include <cuda_runtime.h>
#include <cstdint>

// SquareRotationalLayer ring gather, specialized for H=W=512 (even).
// Split into two kernels:
//   Kernel 1: corner broadcasts + top/bottom row segments (coalesced loads).
//   Kernel 2: left/right column segments via 32x32 smem transpose
//             (coalesced loads AND stores).
//
// Ring dif (0..255): i = 255-dif, el = 2*dif+1, jm = 256+dif = i+el.
// Segment boundaries (prefix of [i,el,2i,el,2i,el,2i,el,i]), total 2044;
// output cols [2044,2048) wrap to cols [0,4).
//
// Closed forms (H=512):
//   right col: out[dif, 511 + r]  = in[r, 256+dif],  r in [255-dif, 255+dif]
//   left  col: out[dif, 2044 - r] = in[r, 255-dif],  r in [256-dif, 256+dif]

static constexpr int HH = 512;
static constexpr int NR = 256;     // output rows (rings)
static constexpr int OW = 2048;    // output cols = 4H
static constexpr int NW = 2044;    // 4H-4 (wrap modulus)

// ---------------- Kernel 1: rows + corners ----------------
__global__ __launch_bounds__(512, 4)
void SqRL_rows_kernel(const float* __restrict__ in, float* __restrict__ out) {
    const int dif   = blockIdx.x;
    const int plane = blockIdx.y;

    const int i  = 255 - dif;
    const int el = 2 * dif + 1;
    const int jm = 256 + dif;

    const int b1 = i,       b2 = b1 + el, b3 = b2 + 2*i, b4 = b3 + el,
              b5 = b4 + 2*i, b6 = b5 + el, b7 = b6 + 2*i, b8 = b7 + el;

    const float* __restrict__ src = in  + (size_t)plane * (HH * HH);
    float*       __restrict__ dst = out + ((size_t)plane * NR + dif) * OW;

    const int jout = threadIdx.x << 2;     // 4 consecutive output cols
    int j0 = jout;
    if (j0 >= NW) j0 -= NW;                // whole group wraps (NW % 4 == 0)

    auto segOf = [&](int j) -> int {
        if (j < b1) return 0;
        if (j < b2) return 1;
        if (j < b3) return 2;
        if (j < b4) return 3;
        if (j < b5) return 4;
        if (j < b6) return 5;
        if (j < b7) return 6;
        if (j < b8) return 7;
        return 8;
    };

    const int s0 = segOf(j0);
    const int s3 = segOf(j0 + 3);

    if (s0 == s3) {
        if (s0 == 3 || s0 == 7) return;    // column interior -> kernel 2
        float4 v;
        if (s0 == 1) {
            // top row: c = i + (j - b1) = j  -> aligned float4
            v = *reinterpret_cast<const float4*>(src + i * HH + j0);
        } else if (s0 == 5) {
            // bottom row (reversed): c(j0+k) = 1533 - (j0+k); c3 = 1530 - j0 (even)
            const int c3 = 1530 - j0;
            float2 a = *reinterpret_cast<const float2*>(src + jm * HH + c3);
            float2 b = *reinterpret_cast<const float2*>(src + jm * HH + c3 + 2);
            v = make_float4(b.y, b.x, a.y, a.x);
        } else {
            int r, c;
            if (s0 == 2)      { r = i;  c = jm; }
            else if (s0 == 4) { r = jm; c = jm; }
            else if (s0 == 6) { r = jm; c = i;  }
            else              { r = i;  c = i;  }   // 0 / 8: corner (i,i)
            const float t = __ldg(src + r * HH + c);
            v = make_float4(t, t, t, t);
        }
        *reinterpret_cast<float4*>(dst + jout) = v;
    } else {
        // segment-straddling group: scalar per element, skip column elems
        #pragma unroll
        for (int k = 0; k < 4; k++) {
            const int j = j0 + k;
            const int s = segOf(j);
            if (s == 3 || s == 7) continue;
            int r, c;
            switch (s) {
                case 1:  r = i;  c = j;              break;
                case 2:  r = i;  c = jm;             break;
                case 4:  r = jm; c = jm;             break;
                case 5:  r = jm; c = jm - (j - b5);  break;
                case 6:  r = jm; c = i;              break;
                default: r = i;  c = i;              break;  // 0 / 8
            }
            dst[jout + k] = __ldg(src + r * HH + c);
        }
    }
}

// ---------------- Kernel 2: column segments via transpose ----------------
// Block = 256 threads (32x8), handles one 32(r) x 32(dif) tile for BOTH
// left and right columns of one plane.
__global__ __launch_bounds__(256, 6)
void SqRL_cols_kernel(const float* __restrict__ in, float* __restrict__ out) {
    const int r0    = blockIdx.x * 32;   // input rows   [r0, r0+32)
    const int d0    = blockIdx.y * 32;   // rings        [d0, d0+32)
    const int plane = blockIdx.z;

    // Early exit: tile fully outside both triangles.
    // valid iff exists (r,dif) in tile with dif >= min(|r-255|, |r-256|)
    int tmin;
    if (r0 + 31 < 255)      tmin = 255 - (r0 + 31);
    else if (r0 > 256)      tmin = r0 - 256;
    else                    tmin = 0;
    if (d0 + 31 < tmin) return;

    __shared__ float sR[32][33];
    __shared__ float sL[32][33];

    const int tx = threadIdx.x & 31;
    const int ty = threadIdx.x >> 5;     // 0..7

    const float* __restrict__ src = in + (size_t)plane * (HH * HH);

    // Coalesced loads: sX[d_local][r_local] = in(r, col(dif))
    #pragma unroll
    for (int yy = 0; yy < 4; yy++) {
        const int rl = ty + 8 * yy;
        const int r  = r0 + rl;
        sR[tx][rl] = __ldg(src + r * HH + (256 + d0 + tx));
        sL[tx][rl] = __ldg(src + r * HH + (255 - d0 - tx));
    }
    __syncthreads();

    const int r   = r0 + tx;
    const int thR = max(255 - r, r - 255);   // right valid iff dif >= thR
    const int thL = max(256 - r, r - 256);   // left  valid iff dif >= thL

    float* __restrict__ dstP = out + (size_t)plane * NR * OW;

    // Coalesced stores along output rows (contiguous in r -> in tx)
    #pragma unroll
    for (int yy = 0; yy < 4; yy++) {
        const int dl  = ty + 8 * yy;
        const int dif = d0 + dl;
        const float vR = sR[dl][tx];
        const float vL = sL[dl][tx];
        float* row = dstP + (size_t)dif * OW;
        if (dif >= thR) row[511 + r]  = vR;   // right column segment
        if (dif >= thL) row[2044 - r] = vL;   // left  column segment
    }
}

extern "C" void kernel_launch(void* const* d_in, const int* in_sizes, int n_in,
                              void* d_out, int out_size) {
    const float* x   = (const float*)d_in[0];
    float*       out = (float*)d_out;

    const int BC = in_sizes[0] / (HH * HH);   // 16*32 = 512 planes

    SqRL_rows_kernel<<<dim3(NR, BC), 512>>>(x, out);
    SqRL_cols_kernel<<<dim3(HH / 32, NR / 32, BC), 256>>>(x, out);
}

// round 7
// speedup vs baseline: 1.3603x; 1.3603x over previous
#include <cuda_runtime.h>
#include <cstdint>

// SquareRotationalLayer ring gather, H=W=512 (even). Two kernels:
//   Kernel 1 (fill): quadrant closed forms for rows/corners/wrap.
//   Kernel 2 (cols): left/right column interiors via 32x32 smem transpose.
//
// Ring dif: i = 255-dif, jm = 256+dif, el = 2*dif+1.
// Exact segment boundaries: b1=i, b2=jm, b3=766-dif, b4=767+dif,
// b5=1277-dif, b6=1278+dif, b7=1788-dif, b8=1789+dif, total 2044, wrap 4.
//
// Quadrant forms (verified incl. b5/b7 crossing quadrant edges at dif>=253):
//   Q1 [0,512):     in[i, clamp(j, i, jm)]
//   Q2 [512,1024):  r=j-511: r<i -> in[i,jm]; i<=r<jm -> KERNEL2;
//                   r>=jm -> in[jm, clamp(1533-j, i, jm)]
//   Q3 [1024,1536): c=1533-j: c>i -> in[jm, min(c,jm)];
//                   c<=i -> in[clamp(2044-j, i, jm), i]
//   Q4 [1536,2048): j<2044: r=2044-j: r<=i -> in[i,i]; i<r<=jm -> KERNEL2;
//                   r>jm -> in[jm,i].   j>=2044: in[i, clamp(j-2044, i, jm)]

static constexpr int HH = 512;
static constexpr int NR = 256;
static constexpr int OW = 2048;

__device__ __forceinline__ int clampi(int x, int lo, int hi) {
    return min(max(x, lo), hi);
}

// ---------------- Kernel 1: quadrant fill ----------------
__global__ __launch_bounds__(512, 4)
void SqRL_fill_kernel(const float* __restrict__ in, float* __restrict__ out) {
    const int dif   = blockIdx.x;
    const int plane = blockIdx.y;
    const int i  = 255 - dif;
    const int jm = 256 + dif;

    const float* __restrict__ src = in  + (size_t)plane * (HH * HH);
    float*       __restrict__ dst = out + ((size_t)plane * NR + dif) * OW;

    const int j0   = threadIdx.x << 2;   // 4 consecutive output cols
    const int quad = threadIdx.x >> 7;   // warp-uniform quadrant

    if (quad == 0) {
        // Q1: in[i, clamp(j, i, jm)]
        const float* __restrict__ row = src + i * HH;
        float4 v;
        if (j0 >= i && j0 + 3 <= jm) {
            v = *reinterpret_cast<const float4*>(row + j0);        // aligned
        } else if (j0 + 3 < i) {
            const float t = __ldg(row + i);  v = make_float4(t, t, t, t);
        } else if (j0 >= jm) {
            const float t = __ldg(row + jm); v = make_float4(t, t, t, t);
        } else {
            v.x = __ldg(row + clampi(j0 + 0, i, jm));
            v.y = __ldg(row + clampi(j0 + 1, i, jm));
            v.z = __ldg(row + clampi(j0 + 2, i, jm));
            v.w = __ldg(row + clampi(j0 + 3, i, jm));
        }
        *reinterpret_cast<float4*>(dst + j0) = v;
    } else if (quad == 1) {
        // Q2: r=j-511
        const int rf = j0 - 511;       // k=0
        const int rl = rf + 3;         // k=3
        if (rl < i) {
            const float t = __ldg(src + i * HH + jm);
            *reinterpret_cast<float4*>(dst + j0) = make_float4(t, t, t, t);
        } else if (rf >= jm) {
            const float* __restrict__ row = src + jm * HH;
            float4 v;
            v.x = __ldg(row + clampi(1533 - (j0 + 0), i, jm));
            v.y = __ldg(row + clampi(1533 - (j0 + 1), i, jm));
            v.z = __ldg(row + clampi(1533 - (j0 + 2), i, jm));
            v.w = __ldg(row + clampi(1533 - (j0 + 3), i, jm));
            *reinterpret_cast<float4*>(dst + j0) = v;
        } else if (rf >= i && rl < jm) {
            // fully interior -> kernel 2
        } else {
            #pragma unroll
            for (int k = 0; k < 4; k++) {
                const int j = j0 + k, r = j - 511;
                if (r < i)        dst[j] = __ldg(src + i * HH + jm);
                else if (r >= jm) dst[j] = __ldg(src + jm * HH + clampi(1533 - j, i, jm));
                // i <= r < jm: kernel 2
            }
        }
    } else if (quad == 2) {
        // Q3: c=1533-j (descending)
        const int cf = 1533 - j0;      // k=0 (max c)
        const int cl = cf - 3;         // k=3 (min c)
        const float* __restrict__ rowjm = src + jm * HH;
        float4 v;
        if (cl > i && cf <= jm) {
            // interior bottom row, reversed; cl = 1530-j0 is even -> 8B aligned
            const float2 a = *reinterpret_cast<const float2*>(rowjm + cl);
            const float2 b = *reinterpret_cast<const float2*>(rowjm + cl + 2);
            v = make_float4(b.y, b.x, a.y, a.x);
        } else if (cl > jm) {
            const float t = __ldg(rowjm + jm); v = make_float4(t, t, t, t);
        } else if (cf <= i && (2041 - j0) >= jm) {
            // fully in corner-7 region (left saturated high)
            const float t = __ldg(rowjm + i);  v = make_float4(t, t, t, t);
        } else {
            #pragma unroll
            for (int k = 0; k < 4; k++) {
                const int j = j0 + k, c = 1533 - j;
                float t;
                if (c <= i) t = __ldg(src + clampi(2044 - j, i, jm) * HH + i);
                else        t = __ldg(rowjm + min(c, jm));
                reinterpret_cast<float*>(&v)[k] = t;
            }
        }
        *reinterpret_cast<float4*>(dst + j0) = v;
    } else {
        // Q4: r=2044-j (descending); wrap at j>=2044
        if (j0 == 2044) {
            const float* __restrict__ row = src + i * HH;
            float4 v;
            v.x = __ldg(row + clampi(0, i, jm));
            v.y = __ldg(row + clampi(1, i, jm));
            v.z = __ldg(row + clampi(2, i, jm));
            v.w = __ldg(row + clampi(3, i, jm));
            *reinterpret_cast<float4*>(dst + j0) = v;
        } else {
            const int rf = 2044 - j0;  // k=0 (max r)
            const int rl = rf - 3;     // k=3 (min r)
            if (rf <= i) {
                const float t = __ldg(src + i * HH + i);
                *reinterpret_cast<float4*>(dst + j0) = make_float4(t, t, t, t);
            } else if (rl > jm) {
                const float t = __ldg(src + jm * HH + i);
                *reinterpret_cast<float4*>(dst + j0) = make_float4(t, t, t, t);
            } else if (rl > i && rf <= jm) {
                // fully interior -> kernel 2
            } else {
                #pragma unroll
                for (int k = 0; k < 4; k++) {
                    const int j = j0 + k, r = 2044 - j;
                    if (r <= i)     dst[j] = __ldg(src + i * HH + i);
                    else if (r > jm) dst[j] = __ldg(src + jm * HH + i);
                    // i < r <= jm: kernel 2
                }
            }
        }
    }
}

// ---------------- Kernel 2: column interiors via transpose ----------------
// Block = 256 threads (32x8): one 32(r) x 32(dif) tile, BOTH columns.
__global__ __launch_bounds__(256, 6)
void SqRL_cols_kernel(const float* __restrict__ in, float* __restrict__ out) {
    const int r0    = blockIdx.x * 32;
    const int d0    = blockIdx.y * 32;
    const int plane = blockIdx.z;

    // Cull tiles fully outside both triangles.
    int tmin;
    if (r0 + 31 < 255)      tmin = 255 - (r0 + 31);
    else if (r0 > 256)      tmin = r0 - 256;
    else                    tmin = 0;
    if (d0 + 31 < tmin) return;

    __shared__ float sR[32][33];
    __shared__ float sL[32][33];

    const int tx = threadIdx.x & 31;
    const int ty = threadIdx.x >> 5;

    const float* __restrict__ src = in + (size_t)plane * (HH * HH);

    #pragma unroll
    for (int yy = 0; yy < 4; yy++) {
        const int rl = ty + 8 * yy;
        const int r  = r0 + rl;
        sR[tx][rl] = __ldg(src + r * HH + (256 + d0 + tx));
        sL[tx][rl] = __ldg(src + r * HH + (255 - d0 - tx));
    }
    __syncthreads();

    const int r   = r0 + tx;
    const int thR = max(255 - r, r - 255);   // right valid iff dif >= thR
    const int thL = max(256 - r, r - 256);   // left  valid iff dif >= thL

    float* __restrict__ dstP = out + (size_t)plane * NR * OW;

    #pragma unroll
    for (int yy = 0; yy < 4; yy++) {
        const int dl  = ty + 8 * yy;
        const int dif = d0 + dl;
        const float vR = sR[dl][tx];
        const float vL = sL[dl][tx];
        float* row = dstP + (size_t)dif * OW;
        if (dif >= thR) row[511 + r]  = vR;   // right column: out[dif, 511+r]
        if (dif >= thL) row[2044 - r] = vL;   // left  column: out[dif, 2044-r]
    }
}

extern "C" void kernel_launch(void* const* d_in, const int* in_sizes, int n_in,
                              void* d_out, int out_size) {
    const float* x   = (const float*)d_in[0];
    float*       out = (float*)d_out;

    const int BC = in_sizes[0] / (HH * HH);   // 16*32 = 512 planes

    SqRL_fill_kernel<<<dim3(NR, BC), 512>>>(x, out);
    SqRL_cols_kernel<<<dim3(HH / 32, NR / 32, BC), 256>>>(x, out);
}

// round 8
// speedup vs baseline: 1.4385x; 1.0575x over previous
#include <cuda_runtime.h>
#include <cstdint>

// SquareRotationalLayer ring gather, H=W=512 (even). Two kernels:
//   Kernel 1 (fill): quadrant closed forms for rows/corners/wrap, 4 rings/block.
//   Kernel 2 (cols): left/right column interiors via 32x32 smem transpose.
//
// Ring dif: i = 255-dif, jm = 256+dif, el = 2*dif+1.
// Quadrant forms (verified incl. b5/b7 crossing quadrant edges at dif>=253):
//   Q1 [0,512):     in[i, clamp(j, i, jm)]
//   Q2 [512,1024):  r=j-511: r<i -> in[i,jm]; i<=r<jm -> KERNEL2;
//                   r>=jm -> in[jm, clamp(1533-j, i, jm)]
//   Q3 [1024,1536): c=1533-j: c>i -> in[jm, min(c,jm)];
//                   c<=i -> in[clamp(2044-j, i, jm), i]
//   Q4 [1536,2048): j<2044: r=2044-j: r<=i -> in[i,i]; i<r<=jm -> KERNEL2;
//                   r>jm -> in[jm,i].   j>=2044: in[i, clamp(j-2044, i, jm)]

static constexpr int HH = 512;
static constexpr int NR = 256;
static constexpr int OW = 2048;

__device__ __forceinline__ int clampi(int x, int lo, int hi) {
    return min(max(x, lo), hi);
}

// ---------------- Kernel 1: quadrant fill, 4 rings per block ----------------
__global__ __launch_bounds__(512, 4)
void SqRL_fill_kernel(const float* __restrict__ in, float* __restrict__ out) {
    const int dif0  = blockIdx.x << 2;   // 4 rings per block
    const int plane = blockIdx.y;

    const float* __restrict__ src  = in  + (size_t)plane * (HH * HH);
    float*       __restrict__ dst0 = out + ((size_t)plane * NR + dif0) * OW;

    const int j0   = threadIdx.x << 2;   // 4 consecutive output cols
    const int quad = threadIdx.x >> 7;   // warp-uniform quadrant

    #pragma unroll
    for (int dd = 0; dd < 4; dd++) {
        const int dif = dif0 + dd;
        const int i  = 255 - dif;
        const int jm = 256 + dif;
        float* __restrict__ dst = dst0 + (size_t)dd * OW;

        if (quad == 0) {
            // Q1: in[i, clamp(j, i, jm)]
            const float* __restrict__ row = src + i * HH;
            float4 v;
            if (j0 >= i && j0 + 3 <= jm) {
                v = *reinterpret_cast<const float4*>(row + j0);    // aligned
            } else if (j0 + 3 < i) {
                const float t = __ldg(row + i);  v = make_float4(t, t, t, t);
            } else if (j0 >= jm) {
                const float t = __ldg(row + jm); v = make_float4(t, t, t, t);
            } else {
                v.x = __ldg(row + clampi(j0 + 0, i, jm));
                v.y = __ldg(row + clampi(j0 + 1, i, jm));
                v.z = __ldg(row + clampi(j0 + 2, i, jm));
                v.w = __ldg(row + clampi(j0 + 3, i, jm));
            }
            *reinterpret_cast<float4*>(dst + j0) = v;
        } else if (quad == 1) {
            // Q2: r=j-511
            const int rf = j0 - 511;       // k=0
            const int rl = rf + 3;         // k=3
            if (rl < i) {
                const float t = __ldg(src + i * HH + jm);
                *reinterpret_cast<float4*>(dst + j0) = make_float4(t, t, t, t);
            } else if (rf >= jm) {
                const float* __restrict__ row = src + jm * HH;
                float4 v;
                v.x = __ldg(row + clampi(1533 - (j0 + 0), i, jm));
                v.y = __ldg(row + clampi(1533 - (j0 + 1), i, jm));
                v.z = __ldg(row + clampi(1533 - (j0 + 2), i, jm));
                v.w = __ldg(row + clampi(1533 - (j0 + 3), i, jm));
                *reinterpret_cast<float4*>(dst + j0) = v;
            } else if (rf >= i && rl < jm) {
                // fully interior -> kernel 2
            } else {
                #pragma unroll
                for (int k = 0; k < 4; k++) {
                    const int j = j0 + k, r = j - 511;
                    if (r < i)        dst[j] = __ldg(src + i * HH + jm);
                    else if (r >= jm) dst[j] = __ldg(src + jm * HH + clampi(1533 - j, i, jm));
                    // i <= r < jm: kernel 2
                }
            }
        } else if (quad == 2) {
            // Q3: c=1533-j (descending)
            const int cf = 1533 - j0;      // k=0 (max c)
            const int cl = cf - 3;         // k=3 (min c)
            const float* __restrict__ rowjm = src + jm * HH;
            float4 v;
            if (cl > i && cf <= jm) {
                // interior bottom row, reversed; cl = 1530-j0 is even -> 8B aligned
                const float2 a = *reinterpret_cast<const float2*>(rowjm + cl);
                const float2 b = *reinterpret_cast<const float2*>(rowjm + cl + 2);
                v = make_float4(b.y, b.x, a.y, a.x);
            } else if (cl > jm) {
                const float t = __ldg(rowjm + jm); v = make_float4(t, t, t, t);
            } else if (cf <= i && (2041 - j0) >= jm) {
                // fully in corner-7 region (left saturated high)
                const float t = __ldg(rowjm + i);  v = make_float4(t, t, t, t);
            } else {
                #pragma unroll
                for (int k = 0; k < 4; k++) {
                    const int j = j0 + k, c = 1533 - j;
                    float t;
                    if (c <= i) t = __ldg(src + clampi(2044 - j, i, jm) * HH + i);
                    else        t = __ldg(rowjm + min(c, jm));
                    reinterpret_cast<float*>(&v)[k] = t;
                }
            }
            *reinterpret_cast<float4*>(dst + j0) = v;
        } else {
            // Q4: r=2044-j (descending); wrap at j>=2044
            if (j0 == 2044) {
                const float* __restrict__ row = src + i * HH;
                float4 v;
                v.x = __ldg(row + clampi(0, i, jm));
                v.y = __ldg(row + clampi(1, i, jm));
                v.z = __ldg(row + clampi(2, i, jm));
                v.w = __ldg(row + clampi(3, i, jm));
                *reinterpret_cast<float4*>(dst + j0) = v;
            } else {
                const int rf = 2044 - j0;  // k=0 (max r)
                const int rl = rf - 3;     // k=3 (min r)
                if (rf <= i) {
                    const float t = __ldg(src + i * HH + i);
                    *reinterpret_cast<float4*>(dst + j0) = make_float4(t, t, t, t);
                } else if (rl > jm) {
                    const float t = __ldg(src + jm * HH + i);
                    *reinterpret_cast<float4*>(dst + j0) = make_float4(t, t, t, t);
                } else if (rl > i && rf <= jm) {
                    // fully interior -> kernel 2
                } else {
                    #pragma unroll
                    for (int k = 0; k < 4; k++) {
                        const int j = j0 + k, r = 2044 - j;
                        if (r <= i)      dst[j] = __ldg(src + i * HH + i);
                        else if (r > jm) dst[j] = __ldg(src + jm * HH + i);
                        // i < r <= jm: kernel 2
                    }
                }
            }
        }
    }
}

// ---------------- Kernel 2: column interiors via transpose ----------------
// Block = 256 threads (32x8): one 32(r) x 32(dif) tile, BOTH columns.
__global__ __launch_bounds__(256, 6)
void SqRL_cols_kernel(const float* __restrict__ in, float* __restrict__ out) {
    const int r0    = blockIdx.x * 32;
    const int d0    = blockIdx.y * 32;
    const int plane = blockIdx.z;

    // Cull tiles fully outside both triangles.
    int tmin;
    if (r0 + 31 < 255)      tmin = 255 - (r0 + 31);
    else if (r0 > 256)      tmin = r0 - 256;
    else                    tmin = 0;
    if (d0 + 31 < tmin) return;

    __shared__ float sR[32][33];
    __shared__ float sL[32][33];

    const int tx = threadIdx.x & 31;     // dif lane within tile
    const int ty = threadIdx.x >> 5;

    const float* __restrict__ src = in + (size_t)plane * (HH * HH);
    const int difv = d0 + tx;

    // Predicated coalesced loads: skip LDG for cells never consumed by a
    // valid store (valid dif range per row is a contiguous suffix in lanes).
    #pragma unroll
    for (int yy = 0; yy < 4; yy++) {
        const int rl = ty + 8 * yy;
        const int r  = r0 + rl;
        const int tR = max(255 - r, r - 255);
        const int tL = max(256 - r, r - 256);
        sR[tx][rl] = (difv >= tR) ? __ldg(src + r * HH + (256 + difv)) : 0.0f;
        sL[tx][rl] = (difv >= tL) ? __ldg(src + r * HH + (255 - difv)) : 0.0f;
    }
    __syncthreads();

    const int r   = r0 + tx;
    const int thR = max(255 - r, r - 255);   // right valid iff dif >= thR
    const int thL = max(256 - r, r - 256);   // left  valid iff dif >= thL

    float* __restrict__ dstP = out + (size_t)plane * NR * OW;

    #pragma unroll
    for (int yy = 0; yy < 4; yy++) {
        const int dl  = ty + 8 * yy;
        const int dif = d0 + dl;
        const float vR = sR[dl][tx];
        const float vL = sL[dl][tx];
        float* row = dstP + (size_t)dif * OW;
        if (dif >= thR) row[511 + r]  = vR;   // right column: out[dif, 511+r]
        if (dif >= thL) row[2044 - r] = vL;   // left  column: out[dif, 2044-r]
    }
}

extern "C" void kernel_launch(void* const* d_in, const int* in_sizes, int n_in,
                              void* d_out, int out_size) {
    const float* x   = (const float*)d_in[0];
    float*       out = (float*)d_out;

    const int BC = in_sizes[0] / (HH * HH);   // 16*32 = 512 planes

    SqRL_fill_kernel<<<dim3(NR / 4, BC), 512>>>(x, out);
    SqRL_cols_kernel<<<dim3(HH / 32, NR / 32, BC), 256>>>(x, out);
}

// round 9
// speedup vs baseline: 1.6202x; 1.1263x over previous
#include <cuda_runtime.h>
#include <cstdint>

// SquareRotationalLayer ring gather, H=W=512 (even). SINGLE fused kernel:
//   blocks x in [0,64):    fill path — quadrant closed forms, 4 rings/block
//   blocks x in [64,192):  cols path — 32x32 smem transpose of L/R column
//                          interiors (16 r-tiles x 8 d-tiles)
// The two paths read-only the input and write disjoint output regions, so
// they can run concurrently; fusing them lets the latency-bound transpose
// blocks overlap with the issue-bound fill blocks.
//
// Ring dif: i = 255-dif, jm = 256+dif, el = 2*dif+1.
// Quadrant forms (verified incl. b5/b7 crossing quadrant edges at dif>=253):
//   Q1 [0,512):     in[i, clamp(j, i, jm)]
//   Q2 [512,1024):  r=j-511: r<i -> in[i,jm]; i<=r<jm -> cols path;
//                   r>=jm -> in[jm, clamp(1533-j, i, jm)]
//   Q3 [1024,1536): c=1533-j: c>i -> in[jm, min(c,jm)];
//                   c<=i -> in[clamp(2044-j, i, jm), i]
//   Q4 [1536,2048): j<2044: r=2044-j: r<=i -> in[i,i]; i<r<=jm -> cols path;
//                   r>jm -> in[jm,i].   j>=2044: in[i, clamp(j-2044, i, jm)]
// Cols closed forms:
//   right: out[dif, 511+r]  = in[r, 256+dif], r in [255-dif, 255+dif]
//   left:  out[dif, 2044-r] = in[r, 255-dif], r in [256-dif, 256+dif]

static constexpr int HH = 512;
static constexpr int NR = 256;
static constexpr int OW = 2048;

__device__ __forceinline__ int clampi(int x, int lo, int hi) {
    return min(max(x, lo), hi);
}

__global__ __launch_bounds__(512, 4)
void SqRL_fused_kernel(const float* __restrict__ in, float* __restrict__ out) {
    __shared__ float sR[32][33];
    __shared__ float sL[32][33];

    const int plane = blockIdx.y;
    const float* __restrict__ src = in + (size_t)plane * (HH * HH);

    if (blockIdx.x < 64) {
        // ================= FILL PATH: 4 rings per block =================
        const int dif0 = blockIdx.x << 2;
        float* __restrict__ dst0 = out + ((size_t)plane * NR + dif0) * OW;

        const int j0   = threadIdx.x << 2;   // 4 consecutive output cols
        const int quad = threadIdx.x >> 7;   // warp-uniform quadrant

        #pragma unroll
        for (int dd = 0; dd < 4; dd++) {
            const int dif = dif0 + dd;
            const int i  = 255 - dif;
            const int jm = 256 + dif;
            float* __restrict__ dst = dst0 + (size_t)dd * OW;

            if (quad == 0) {
                // Q1: in[i, clamp(j, i, jm)]
                const float* __restrict__ row = src + i * HH;
                float4 v;
                if (j0 >= i && j0 + 3 <= jm) {
                    v = *reinterpret_cast<const float4*>(row + j0);   // aligned
                } else if (j0 + 3 < i) {
                    const float t = __ldg(row + i);  v = make_float4(t, t, t, t);
                } else if (j0 >= jm) {
                    const float t = __ldg(row + jm); v = make_float4(t, t, t, t);
                } else {
                    v.x = __ldg(row + clampi(j0 + 0, i, jm));
                    v.y = __ldg(row + clampi(j0 + 1, i, jm));
                    v.z = __ldg(row + clampi(j0 + 2, i, jm));
                    v.w = __ldg(row + clampi(j0 + 3, i, jm));
                }
                *reinterpret_cast<float4*>(dst + j0) = v;
            } else if (quad == 1) {
                // Q2: r=j-511
                const int rf = j0 - 511;       // k=0
                const int rl = rf + 3;         // k=3
                if (rl < i) {
                    const float t = __ldg(src + i * HH + jm);
                    *reinterpret_cast<float4*>(dst + j0) = make_float4(t, t, t, t);
                } else if (rf >= jm) {
                    const float* __restrict__ row = src + jm * HH;
                    float4 v;
                    v.x = __ldg(row + clampi(1533 - (j0 + 0), i, jm));
                    v.y = __ldg(row + clampi(1533 - (j0 + 1), i, jm));
                    v.z = __ldg(row + clampi(1533 - (j0 + 2), i, jm));
                    v.w = __ldg(row + clampi(1533 - (j0 + 3), i, jm));
                    *reinterpret_cast<float4*>(dst + j0) = v;
                } else if (rf >= i && rl < jm) {
                    // fully interior -> cols path
                } else {
                    #pragma unroll
                    for (int k = 0; k < 4; k++) {
                        const int j = j0 + k, r = j - 511;
                        if (r < i)        dst[j] = __ldg(src + i * HH + jm);
                        else if (r >= jm) dst[j] = __ldg(src + jm * HH + clampi(1533 - j, i, jm));
                        // i <= r < jm: cols path
                    }
                }
            } else if (quad == 2) {
                // Q3: c=1533-j (descending)
                const int cf = 1533 - j0;      // k=0 (max c)
                const int cl = cf - 3;         // k=3 (min c)
                const float* __restrict__ rowjm = src + jm * HH;
                float4 v;
                if (cl > i && cf <= jm) {
                    // interior bottom row, reversed; cl = 1530-j0 even -> 8B aligned
                    const float2 a = *reinterpret_cast<const float2*>(rowjm + cl);
                    const float2 b = *reinterpret_cast<const float2*>(rowjm + cl + 2);
                    v = make_float4(b.y, b.x, a.y, a.x);
                } else if (cl > jm) {
                    const float t = __ldg(rowjm + jm); v = make_float4(t, t, t, t);
                } else if (cf <= i && (2041 - j0) >= jm) {
                    const float t = __ldg(rowjm + i);  v = make_float4(t, t, t, t);
                } else {
                    #pragma unroll
                    for (int k = 0; k < 4; k++) {
                        const int j = j0 + k, c = 1533 - j;
                        float t;
                        if (c <= i) t = __ldg(src + clampi(2044 - j, i, jm) * HH + i);
                        else        t = __ldg(rowjm + min(c, jm));
                        reinterpret_cast<float*>(&v)[k] = t;
                    }
                }
                *reinterpret_cast<float4*>(dst + j0) = v;
            } else {
                // Q4: r=2044-j (descending); wrap at j>=2044
                if (j0 == 2044) {
                    const float* __restrict__ row = src + i * HH;
                    float4 v;
                    v.x = __ldg(row + clampi(0, i, jm));
                    v.y = __ldg(row + clampi(1, i, jm));
                    v.z = __ldg(row + clampi(2, i, jm));
                    v.w = __ldg(row + clampi(3, i, jm));
                    *reinterpret_cast<float4*>(dst + j0) = v;
                } else {
                    const int rf = 2044 - j0;  // k=0 (max r)
                    const int rl = rf - 3;     // k=3 (min r)
                    if (rf <= i) {
                        const float t = __ldg(src + i * HH + i);
                        *reinterpret_cast<float4*>(dst + j0) = make_float4(t, t, t, t);
                    } else if (rl > jm) {
                        const float t = __ldg(src + jm * HH + i);
                        *reinterpret_cast<float4*>(dst + j0) = make_float4(t, t, t, t);
                    } else if (rl > i && rf <= jm) {
                        // fully interior -> cols path
                    } else {
                        #pragma unroll
                        for (int k = 0; k < 4; k++) {
                            const int j = j0 + k, r = 2044 - j;
                            if (r <= i)      dst[j] = __ldg(src + i * HH + i);
                            else if (r > jm) dst[j] = __ldg(src + jm * HH + i);
                            // i < r <= jm: cols path
                        }
                    }
                }
            }
        }
    } else {
        // ================= COLS PATH: 32x32 transpose tile =================
        const int cx = blockIdx.x - 64;        // 0..127
        const int r0 = (cx & 15) * 32;         // input rows [r0, r0+32)
        const int d0 = (cx >> 4) * 32;         // rings      [d0, d0+32)

        // Cull tiles fully outside both triangles.
        int tmin;
        if (r0 + 31 < 255)      tmin = 255 - (r0 + 31);
        else if (r0 > 256)      tmin = r0 - 256;
        else                    tmin = 0;
        if (d0 + 31 < tmin) return;

        const int tx = threadIdx.x & 31;       // dif lane on load / r lane on store
        const int ty = threadIdx.x >> 5;       // 0..15

        // Coalesced loads: s*[d_local][r_local] = in(r, col(dif))
        #pragma unroll
        for (int yy = 0; yy < 2; yy++) {
            const int rl = ty + 16 * yy;
            const int r  = r0 + rl;
            sR[tx][rl] = __ldg(src + r * HH + (256 + d0 + tx));
            sL[tx][rl] = __ldg(src + r * HH + (255 - d0 - tx));
        }
        __syncthreads();

        const int r   = r0 + tx;
        const int thR = max(255 - r, r - 255);   // right valid iff dif >= thR
        const int thL = max(256 - r, r - 256);   // left  valid iff dif >= thL

        float* __restrict__ dstP = out + (size_t)plane * NR * OW;

        #pragma unroll
        for (int yy = 0; yy < 2; yy++) {
            const int dl  = ty + 16 * yy;
            const int dif = d0 + dl;
            const float vR = sR[dl][tx];
            const float vL = sL[dl][tx];
            float* row = dstP + (size_t)dif * OW;
            if (dif >= thR) row[511 + r]  = vR;   // right: out[dif, 511+r]
            if (dif >= thL) row[2044 - r] = vL;   // left:  out[dif, 2044-r]
        }
    }
}

extern "C" void kernel_launch(void* const* d_in, const int* in_sizes, int n_in,
                              void* d_out, int out_size) {
    const float* x   = (const float*)d_in[0];
    float*       out = (float*)d_out;

    const int BC = in_sizes[0] / (HH * HH);   // 16*32 = 512 planes

    // x: [0,64) fill blocks (4 rings each), [64,192) cols tiles (16 x 8)
    SqRL_fused_kernel<<<dim3(192, BC), 512>>>(x, out);
}

// round 10
// speedup vs baseline: 1.7900x; 1.1048x over previous
#include <cuda_runtime.h>
#include <cstdint>

// SquareRotationalLayer ring gather, H=W=512 (even). SINGLE fused kernel:
//   blocks x in [0,64):   fill path — quadrant closed forms, 4 rings/block
//   blocks x in [64,128): cols path — 32(r) x 64(d) smem transpose of L/R
//                         column interiors (16 r-tiles x 4 d-tiles)
//
// Ring dif: i = 255-dif, jm = 256+dif.
// Quadrant forms (verified incl. b5/b7 crossing quadrant edges at dif>=253):
//   Q1 [0,512):     in[i, clamp(j, i, jm)]
//   Q2 [512,1024):  r=j-511: r<i -> in[i,jm]; i<=r<jm -> cols path;
//                   r>=jm -> in[jm, clamp(1533-j, i, jm)]
//   Q3 [1024,1536): c=1533-j: c>i -> in[jm, min(c,jm)];
//                   c<=i -> in[clamp(2044-j, i, jm), i]
//   Q4 [1536,2048): j<2044: r=2044-j: r<=i -> in[i,i]; i<r<=jm -> cols path;
//                   r>jm -> in[jm,i].   j>=2044: in[i, clamp(j-2044, i, jm)]
// Cols closed forms:
//   right: out[dif, 511+r]  = in[r, 256+dif], r in [255-dif, 255+dif]
//   left:  out[dif, 2044-r] = in[r, 255-dif], r in [256-dif, 256+dif]

static constexpr int HH = 512;
static constexpr int NR = 256;
static constexpr int OW = 2048;

__device__ __forceinline__ int clampi(int x, int lo, int hi) {
    return min(max(x, lo), hi);
}

__global__ __launch_bounds__(512, 4)
void SqRL_fused_kernel(const float* __restrict__ in, float* __restrict__ out) {
    __shared__ float sR[64][33];   // [d_local][r_local], padded
    __shared__ float sL[64][33];

    const int plane = blockIdx.y;
    const float* __restrict__ src = in + (size_t)plane * (HH * HH);

    if (blockIdx.x < 64) {
        // ================= FILL PATH: 4 rings per block =================
        const int dif0 = blockIdx.x << 2;
        float* __restrict__ dst0 = out + ((size_t)plane * NR + dif0) * OW;

        const int j0   = threadIdx.x << 2;   // 4 consecutive output cols
        const int quad = threadIdx.x >> 7;   // warp-uniform quadrant

        #pragma unroll
        for (int dd = 0; dd < 4; dd++) {
            const int dif = dif0 + dd;
            const int i  = 255 - dif;
            const int jm = 256 + dif;
            float* __restrict__ dst = dst0 + (size_t)dd * OW;

            if (quad == 0) {
                // Q1: in[i, clamp(j, i, jm)]
                const float* __restrict__ row = src + i * HH;
                float4 v;
                if (j0 >= i && j0 + 3 <= jm) {
                    v = *reinterpret_cast<const float4*>(row + j0);   // aligned
                } else if (j0 + 3 < i) {
                    const float t = __ldg(row + i);  v = make_float4(t, t, t, t);
                } else if (j0 >= jm) {
                    const float t = __ldg(row + jm); v = make_float4(t, t, t, t);
                } else {
                    v.x = __ldg(row + clampi(j0 + 0, i, jm));
                    v.y = __ldg(row + clampi(j0 + 1, i, jm));
                    v.z = __ldg(row + clampi(j0 + 2, i, jm));
                    v.w = __ldg(row + clampi(j0 + 3, i, jm));
                }
                *reinterpret_cast<float4*>(dst + j0) = v;
            } else if (quad == 1) {
                // Q2: r=j-511
                const int rf = j0 - 511;       // k=0
                const int rl = rf + 3;         // k=3
                if (rl < i) {
                    const float t = __ldg(src + i * HH + jm);
                    *reinterpret_cast<float4*>(dst + j0) = make_float4(t, t, t, t);
                } else if (rf >= jm) {
                    const float* __restrict__ row = src + jm * HH;
                    float4 v;
                    v.x = __ldg(row + clampi(1533 - (j0 + 0), i, jm));
                    v.y = __ldg(row + clampi(1533 - (j0 + 1), i, jm));
                    v.z = __ldg(row + clampi(1533 - (j0 + 2), i, jm));
                    v.w = __ldg(row + clampi(1533 - (j0 + 3), i, jm));
                    *reinterpret_cast<float4*>(dst + j0) = v;
                } else if (rf >= i && rl < jm) {
                    // fully interior -> cols path
                } else {
                    #pragma unroll
                    for (int k = 0; k < 4; k++) {
                        const int j = j0 + k, r = j - 511;
                        if (r < i)        dst[j] = __ldg(src + i * HH + jm);
                        else if (r >= jm) dst[j] = __ldg(src + jm * HH + clampi(1533 - j, i, jm));
                        // i <= r < jm: cols path
                    }
                }
            } else if (quad == 2) {
                // Q3: c=1533-j (descending)
                const int cf = 1533 - j0;      // k=0 (max c)
                const int cl = cf - 3;         // k=3 (min c)
                const float* __restrict__ rowjm = src + jm * HH;
                float4 v;
                if (cl > i && cf <= jm) {
                    // interior bottom row, reversed; cl = 1530-j0 even -> 8B aligned
                    const float2 a = *reinterpret_cast<const float2*>(rowjm + cl);
                    const float2 b = *reinterpret_cast<const float2*>(rowjm + cl + 2);
                    v = make_float4(b.y, b.x, a.y, a.x);
                } else if (cl > jm) {
                    const float t = __ldg(rowjm + jm); v = make_float4(t, t, t, t);
                } else if (cf <= i && (2041 - j0) >= jm) {
                    const float t = __ldg(rowjm + i);  v = make_float4(t, t, t, t);
                } else {
                    #pragma unroll
                    for (int k = 0; k < 4; k++) {
                        const int j = j0 + k, c = 1533 - j;
                        float t;
                        if (c <= i) t = __ldg(src + clampi(2044 - j, i, jm) * HH + i);
                        else        t = __ldg(rowjm + min(c, jm));
                        reinterpret_cast<float*>(&v)[k] = t;
                    }
                }
                *reinterpret_cast<float4*>(dst + j0) = v;
            } else {
                // Q4: r=2044-j (descending); wrap at j>=2044
                if (j0 == 2044) {
                    const float* __restrict__ row = src + i * HH;
                    float4 v;
                    v.x = __ldg(row + clampi(0, i, jm));
                    v.y = __ldg(row + clampi(1, i, jm));
                    v.z = __ldg(row + clampi(2, i, jm));
                    v.w = __ldg(row + clampi(3, i, jm));
                    *reinterpret_cast<float4*>(dst + j0) = v;
                } else {
                    const int rf = 2044 - j0;  // k=0 (max r)
                    const int rl = rf - 3;     // k=3 (min r)
                    if (rf <= i) {
                        const float t = __ldg(src + i * HH + i);
                        *reinterpret_cast<float4*>(dst + j0) = make_float4(t, t, t, t);
                    } else if (rl > jm) {
                        const float t = __ldg(src + jm * HH + i);
                        *reinterpret_cast<float4*>(dst + j0) = make_float4(t, t, t, t);
                    } else if (rl > i && rf <= jm) {
                        // fully interior -> cols path
                    } else {
                        #pragma unroll
                        for (int k = 0; k < 4; k++) {
                            const int j = j0 + k, r = 2044 - j;
                            if (r <= i)      dst[j] = __ldg(src + i * HH + i);
                            else if (r > jm) dst[j] = __ldg(src + jm * HH + i);
                            // i < r <= jm: cols path
                        }
                    }
                }
            }
        }
    } else {
        // ============ COLS PATH: 32(r) x 64(d) transpose tile ============
        const int cx = blockIdx.x - 64;        // 0..63
        const int r0 = (cx & 15) * 32;         // input rows [r0, r0+32)
        const int d0 = (cx >> 4) * 64;         // rings      [d0, d0+64)

        // Cull tiles fully outside both triangles.
        int tmin;
        if (r0 + 31 < 255)      tmin = 255 - (r0 + 31);
        else if (r0 > 256)      tmin = r0 - 256;
        else                    tmin = 0;
        if (d0 + 63 < tmin) return;

        // ---- load phase: lanes span 64 d-values ----
        {
            const int dx = threadIdx.x & 63;   // d lane 0..63
            const int ry = threadIdx.x >> 6;   // 0..7
            #pragma unroll
            for (int yy = 0; yy < 4; yy++) {
                const int rl = ry + 8 * yy;
                const int r  = r0 + rl;
                sR[dx][rl] = __ldg(src + r * HH + (256 + d0 + dx));
                sL[dx][rl] = __ldg(src + r * HH + (255 - d0 - dx));
            }
        }
        __syncthreads();

        // ---- store phase: lanes span 32 r-values (coalesced out rows) ----
        const int rx = threadIdx.x & 31;       // r lane 0..31
        const int dy = threadIdx.x >> 5;       // 0..15

        const int r   = r0 + rx;
        const int thR = max(255 - r, r - 255); // right valid iff dif >= thR
        const int thL = max(256 - r, r - 256); // left  valid iff dif >= thL

        float* __restrict__ dstP = out + (size_t)plane * NR * OW;

        #pragma unroll
        for (int yy = 0; yy < 4; yy++) {
            const int dl  = dy + 16 * yy;      // 0..63
            const int dif = d0 + dl;
            const float vR = sR[dl][rx];
            const float vL = sL[dl][rx];
            float* row = dstP + (size_t)dif * OW;
            if (dif >= thR) row[511 + r]  = vR;   // right: out[dif, 511+r]
            if (dif >= thL) row[2044 - r] = vL;   // left:  out[dif, 2044-r]
        }
    }
}

extern "C" void kernel_launch(void* const* d_in, const int* in_sizes, int n_in,
                              void* d_out, int out_size) {
    const float* x   = (const float*)d_in[0];
    float*       out = (float*)d_out;

    const int BC = in_sizes[0] / (HH * HH);   // 16*32 = 512 planes

    // x: [0,64) fill blocks (4 rings each), [64,128) cols tiles (16 r x 4 d)
    SqRL_fused_kernel<<<dim3(128, BC), 512>>>(x, out);
}